// round 17
// baseline (speedup 1.0000x reference)
#include <cuda_runtime.h>
#include <cuda_fp16.h>
#include <math.h>
#include <stdint.h>

// Problem constants
#define BATCH   2
#define TSEQ    2048
#define BT      4096          // BATCH*TSEQ
#define DM      512
#define NH      8
#define DH      64
#define DV      64
#define CHUNK   64
#define NCHUNK  (TSEQ / CHUNK)   // 32
#define NBH     (BATCH * NH)     // 16

// ---------------- scratch (device globals; no allocation allowed) ----------
__device__ float g_ksum[NBH * NCHUNK * DH];
__device__ float g_zpre[NBH * NCHUNK * DH];
__device__ int   g_tile_ctr;

// fp16 operands (hi/lo residual splits where needed)
__device__ __half g_xh[BT * DM];
__device__ __half g_Ah[BT * DM];                     // attention output (hi only)
__device__ __half g_Qh[BT * DM],  g_Ql[BT * DM];
__device__ __half g_Kh[BT * DM];
__device__ __half g_Vh[BT * DM];
__device__ __half g_KtVh[NBH * NCHUNK * DH * DV];
__device__ __half g_Sth[NBH * NCHUNK * DH * DV];
__device__ __half g_Wqh[DM * DM], g_Wkh[DM * DM];
__device__ __half g_Wvh[DM * DM], g_Woh[DM * DM];

// ============================================================================
// Helpers
// ============================================================================
__device__ __forceinline__ uint32_t smem_u32(const void* p) {
    uint32_t a;
    asm("{ .reg .u64 t; cvta.to.shared.u64 t, %1; cvt.u32.u64 %0, t; }"
        : "=r"(a) : "l"(p));
    return a;
}

__device__ __forceinline__ uint32_t pack_h2(__half a, __half b) {
    return (uint32_t)__half_as_ushort(a) |
           ((uint32_t)__half_as_ushort(b) << 16);
}

__device__ __forceinline__ void split2u(float v0, float v1,
                                        uint32_t& hi, uint32_t& lo) {
    __half h0 = __float2half_rn(v0);
    __half h1 = __float2half_rn(v1);
    __half l0 = __float2half_rn(v0 - __half2float(h0));
    __half l1 = __float2half_rn(v1 - __half2float(h1));
    hi = pack_h2(h0, h1);
    lo = pack_h2(l0, l1);
}

// phi(t) = elu(t) + 1
__device__ __forceinline__ float elu1(float t) {
    return (t > 0.f) ? (t + 1.f) : __expf(t);
}

// warp mma: D(16x8,f32) += A(16x16,f16,row) * B(16x8,f16,col)
__device__ __forceinline__ void mma16816(float d[4], const uint32_t a[4],
                                         const uint32_t b[2]) {
    asm("mma.sync.aligned.m16n8k16.row.col.f32.f16.f16.f32 "
        "{%0,%1,%2,%3}, {%4,%5,%6,%7}, {%8,%9}, {%0,%1,%2,%3};"
        : "+f"(d[0]), "+f"(d[1]), "+f"(d[2]), "+f"(d[3])
        : "r"(a[0]), "r"(a[1]), "r"(a[2]), "r"(a[3]), "r"(b[0]), "r"(b[1]));
}

__device__ __forceinline__ void ldmx4(uint32_t r[4], uint32_t addr) {
    asm volatile("ldmatrix.sync.aligned.m8n8.x4.shared.b16 {%0,%1,%2,%3}, [%4];"
                 : "=r"(r[0]), "=r"(r[1]), "=r"(r[2]), "=r"(r[3]) : "r"(addr));
}
__device__ __forceinline__ void ldmx4t(uint32_t r[4], uint32_t addr) {
    asm volatile("ldmatrix.sync.aligned.m8n8.x4.trans.shared.b16 {%0,%1,%2,%3}, [%4];"
                 : "=r"(r[0]), "=r"(r[1]), "=r"(r[2]), "=r"(r[3]) : "r"(addr));
}

__device__ __forceinline__ void cp16(uint32_t saddr, const void* g) {
    asm volatile("cp.async.cg.shared.global [%0], [%1], 16;"
                 :: "r"(saddr), "l"(g) : "memory");
}
#define CP_COMMIT() asm volatile("cp.async.commit_group;" ::: "memory")
#define CP_WAIT(n)  asm volatile("cp.async.wait_group %0;" :: "n"(n) : "memory")

// ---------------------------------------------------------------------------
// Kernel 0: merged conversions (fp32 -> fp16 hi) + tile-counter reset.
// ---------------------------------------------------------------------------
__global__ __launch_bounds__(256)
void split_all(const float* __restrict__ x,
               const float* __restrict__ w0, const float* __restrict__ w1,
               const float* __restrict__ w2, const float* __restrict__ w3)
{
    const int bx = blockIdx.x;
    if (bx == 0 && threadIdx.x == 0) g_tile_ctr = 0;
    const float* src;
    __half* dh;
    int i;
    if (bx < 2048) {
        src = x; dh = g_xh;
        i = (bx * 256 + threadIdx.x) * 4;
        if (i >= BT * DM) return;
    } else {
        const int sel = (bx - 2048) >> 8;
        src = (sel == 0) ? w0 : (sel == 1) ? w1 : (sel == 2) ? w2 : w3;
        dh  = (sel == 0) ? g_Wqh : (sel == 1) ? g_Wkh
            : (sel == 2) ? g_Wvh : g_Woh;
        i = (((bx - 2048) & 255) * 256 + threadIdx.x) * 4;
        if (i >= DM * DM) return;
    }
    float4 f = *(const float4*)(src + i);
    *(uint2*)(dh + i) = make_uint2(
        pack_h2(__float2half_rn(f.x), __float2half_rn(f.y)),
        pack_h2(__float2half_rn(f.z), __float2half_rn(f.w)));
}

// ============================================================================
// Tensor-core GEMM tile: C[m,n] = sum_k Ah[m,k]*Bh[n,k]   (1-term fp16)
// Block 128x128, BK=64, 8 warps (4m x 2n), warp tile 32x64, 256 threads,
// 2 CTAs/SM. 3-stage cp.async pipeline; reg-level fragment double-buffer.
// ============================================================================
#define PITCH   72
#define TILE_E  (128 * PITCH)
#define TILE_B  (TILE_E * 2)         // 18432 B
#define NSTAGE  3
#define NTHR    256
#define STAGE_B (2 * TILE_B)         // A + B  = 36864
#define SMEM_GEMM_BYTES (NSTAGE * STAGE_B)  // 110592 -> 2 CTAs/SM
#define NTILES_QKV 384
#define GRID_PERS  296               // 2 * 148 SMs

__device__ __forceinline__ void tc_gemm_128x128(
    const __half* __restrict__ Ahp, const __half* __restrict__ Bhp,
    int m0, int n0, float* __restrict__ Cf,
    __half* __restrict__ Ch, __half* __restrict__ Cl, bool act)
{
    extern __shared__ __half sb[];
    const uint32_t smb = smem_u32(sb);

    const int tid  = threadIdx.x;
    const int w    = tid >> 5;
    const int lane = tid & 31;
    const int g    = lane >> 2;
    const int q    = lane & 3;
    const int wm   = (w >> 1) * 32;   // 4 m-groups
    const int wn   = (w & 1) * 64;    // 2 n-groups

    const int row = tid >> 1;         // 0..127
    const int kh  = (tid & 1) * 32;   // half-row (32 elems)
    const uint32_t sOff = (uint32_t)(row * PITCH + kh) * 2;

    const int sel = lane >> 3;
    const int rr  = lane & 7;
    const uint32_t aBase = smb +
        (uint32_t)(((wm + (sel & 1) * 8 + rr) * PITCH) + (sel >> 1) * 8) * 2;
    const uint32_t bBase = smb + TILE_B +
        (uint32_t)(((wn + (sel >> 1) * 8 + rr) * PITCH) + (sel & 1) * 8) * 2;

    float acc[2][8][4];
    #pragma unroll
    for (int mi = 0; mi < 2; mi++)
        #pragma unroll
        for (int ni = 0; ni < 8; ni++)
            #pragma unroll
            for (int r = 0; r < 4; r++) acc[mi][ni][r] = 0.f;

    auto issue = [&](int c, int s) {
        const uint32_t base = smb + (uint32_t)s * STAGE_B;
        const __half* gA = Ahp + (size_t)(m0 + row) * DM + c * 64 + kh;
        const __half* gB = Bhp + (size_t)(n0 + row) * DM + c * 64 + kh;
        #pragma unroll
        for (int i = 0; i < 4; i++) {
            cp16(base + sOff + i * 16, gA + i * 8);
            cp16(base + TILE_B + sOff + i * 16, gB + i * 8);
        }
        CP_COMMIT();
    };

    issue(0, 0);
    issue(1, 1);

    uint32_t a[2][2][4], b[2][4][4];   // double-buffered fragments

    auto ldfrag = [&](uint32_t stage, int kk, int buf) {
        const uint32_t ko = (uint32_t)kk * 32;
        #pragma unroll
        for (int mi = 0; mi < 2; mi++)
            ldmx4(a[buf][mi], aBase + stage + (uint32_t)mi * 16 * PITCH * 2 + ko);
        #pragma unroll
        for (int nb = 0; nb < 4; nb++)
            ldmx4(b[buf][nb], bBase + stage + (uint32_t)nb * 16 * PITCH * 2 + ko);
    };

    int s = 0;
    #pragma unroll 1
    for (int c = 0; c < 8; c++) {
        if (c == 7) { CP_WAIT(0); } else { CP_WAIT(1); }
        __syncthreads();
        if (c + 2 < 8) {
            int s2 = s + 2 >= NSTAGE ? s + 2 - NSTAGE : s + 2;
            issue(c + 2, s2);
        }

        const uint32_t stage = (uint32_t)s * STAGE_B;

        ldfrag(stage, 0, 0);
        #pragma unroll
        for (int kk = 0; kk < 4; kk++) {
            if (kk < 3) ldfrag(stage, kk + 1, (kk + 1) & 1);
            const int buf = kk & 1;
            #pragma unroll
            for (int mi = 0; mi < 2; mi++)
                #pragma unroll
                for (int ni = 0; ni < 8; ni++)
                    mma16816(acc[mi][ni], a[buf][mi],
                             &b[buf][ni >> 1][(ni & 1) * 2]);
        }
        s = (s + 1 >= NSTAGE) ? 0 : s + 1;
    }

    // epilogue
    #pragma unroll
    for (int mi = 0; mi < 2; mi++) {
        const int r0 = m0 + wm + mi * 16 + g;
        #pragma unroll
        for (int ni = 0; ni < 8; ni++) {
            const int col = n0 + wn + ni * 8 + q * 2;
            float v0 = acc[mi][ni][0], v1 = acc[mi][ni][1];
            float v2 = acc[mi][ni][2], v3 = acc[mi][ni][3];
            if (act) { v0 = elu1(v0); v1 = elu1(v1); v2 = elu1(v2); v3 = elu1(v3); }
            if (Cf) {
                *(float2*)(Cf + (size_t)r0 * DM + col)       = make_float2(v0, v1);
                *(float2*)(Cf + (size_t)(r0 + 8) * DM + col) = make_float2(v2, v3);
            } else if (Cl) {
                uint32_t h, l;
                split2u(v0, v1, h, l);
                *(uint32_t*)(Ch + (size_t)r0 * DM + col) = h;
                *(uint32_t*)(Cl + (size_t)r0 * DM + col) = l;
                split2u(v2, v3, h, l);
                *(uint32_t*)(Ch + (size_t)(r0 + 8) * DM + col) = h;
                *(uint32_t*)(Cl + (size_t)(r0 + 8) * DM + col) = l;
            } else {
                *(uint32_t*)(Ch + (size_t)r0 * DM + col) =
                    pack_h2(__float2half_rn(v0), __float2half_rn(v1));
                *(uint32_t*)(Ch + (size_t)(r0 + 8) * DM + col) =
                    pack_h2(__float2half_rn(v2), __float2half_rn(v3));
            }
        }
    }
}

// ---------------------------------------------------------------------------
// Kernel 1: persistent fused QKV projection (1-term). grid = 296 CTAs.
// Tiles grabbed from a global atomic queue (reset by split_all).
// ---------------------------------------------------------------------------
__global__ __launch_bounds__(NTHR, 2)
void gemm_qkv_tc()
{
    __shared__ int s_tile;
    for (;;) {
        __syncthreads();   // protect smem (stages + s_tile) across tiles
        if (threadIdx.x == 0) s_tile = atomicAdd(&g_tile_ctr, 1);
        __syncthreads();
        const int t = s_tile;
        if (t >= NTILES_QKV) return;

        const int m0 = (t & 31) * 128;
        const int y  = t >> 5;          // 0..11
        const int w  = y >> 2;
        const int n0 = (y & 3) * 128;
        const __half* Bh = (w == 0) ? g_Wqh : (w == 1) ? g_Wkh : g_Wvh;
        __half* Ch = (w == 0) ? g_Qh : (w == 1) ? g_Kh : g_Vh;
        __half* Cl = (w == 0) ? g_Ql : nullptr;
        tc_gemm_128x128(g_xh, Bh, m0, n0, nullptr, Ch, Cl, w < 2);
    }
}

// ---------------------------------------------------------------------------
// Kernel 5: output projection (1-term) -> fp32 out. grid = (32, 4), 1 wave.
// ---------------------------------------------------------------------------
__global__ __launch_bounds__(NTHR, 2)
void gemm_out_tc(float* __restrict__ out)
{
    tc_gemm_128x128(g_Ah, g_Woh, blockIdx.x * 128, blockIdx.y * 128, out,
                    nullptr, nullptr, false);
}

// ============================================================================
// Middle stage: 64x64x64 tensor-core GEMMs. 8 warps/block.
// ============================================================================
#define APITCH  72
#define ATILE_E (64 * APITCH)
#define ATILE_B (ATILE_E * 2)        // 9216 B

// ---------------------------------------------------------------------------
// Kernel 2: per-chunk K^T V + ksum. Kh^T x Vh : 1 term. fp16 KtV output.
// ---------------------------------------------------------------------------
#define SMEM_KV_BYTES (2 * ATILE_B)

__global__ __launch_bounds__(256)
void chunk_kv_mma()
{
    extern __shared__ __half ksb[];
    const uint32_t smb = smem_u32(ksb);
    const int c  = blockIdx.x;
    const int bh = blockIdx.y;
    const int b  = bh >> 3, h = bh & 7;
    const int tid  = threadIdx.x;
    const int w    = tid >> 5;
    const int lane = tid & 31;
    const int g    = lane >> 2, q = lane & 3;
    const int sel  = lane >> 3, rr = lane & 7;
    const int wm   = (w >> 1) * 16;   // i
    const int wn   = (w & 1) * 32;    // j

    const size_t grow = (size_t)(b * TSEQ + c * CHUNK);
    const __half* srcs[2] = {
        g_Kh + grow * DM + h * DH, g_Vh + grow * DM + h * DH };
    #pragma unroll
    for (int t = 0; t < 2; t++)
        #pragma unroll
        for (int it = 0; it < 2; it++) {
            int idx = tid + it * 256;
            int r = idx >> 3, sg = idx & 7;
            *(uint4*)(ksb + t * ATILE_E + r * APITCH + sg * 8) =
                *(const uint4*)(srcs[t] + (size_t)r * DM + sg * 8);
        }
    __syncthreads();

    const uint32_t aK = smb +
        (uint32_t)((((sel >> 1) * 8 + rr) * APITCH) + wm + (sel & 1) * 8) * 2;
    const uint32_t bV = smb + ATILE_B +
        (uint32_t)((((sel & 1) * 8 + rr) * APITCH) + (sel >> 1) * 8) * 2;

    float acc[4][4];
    #pragma unroll
    for (int ni = 0; ni < 4; ni++)
        #pragma unroll
        for (int r = 0; r < 4; r++) acc[ni][r] = 0.f;

    #pragma unroll
    for (int kk = 0; kk < 4; kk++) {
        const uint32_t kro = (uint32_t)kk * 16 * APITCH * 2;
        uint32_t ah[4], bhf[2][4];
        ldmx4t(ah, aK + kro);
        #pragma unroll
        for (int nb = 0; nb < 2; nb++)
            ldmx4t(bhf[nb], bV + kro + (uint32_t)(wn + nb * 16) * 2);
        #pragma unroll
        for (int ni = 0; ni < 4; ni++)
            mma16816(acc[ni], ah, &bhf[ni >> 1][(ni & 1) * 2]);
    }

    __half* dst = g_KtVh + (size_t)(bh * NCHUNK + c) * (DH * DV);
    #pragma unroll
    for (int ni = 0; ni < 4; ni++) {
        const int jj = wn + ni * 8 + q * 2;
        *(uint32_t*)(dst + (wm + g) * DV + jj) =
            pack_h2(__float2half_rn(acc[ni][0]), __float2half_rn(acc[ni][1]));
        *(uint32_t*)(dst + (wm + g + 8) * DV + jj) =
            pack_h2(__float2half_rn(acc[ni][2]), __float2half_rn(acc[ni][3]));
    }

    if (tid < DH) {
        float s = 0.f;
        #pragma unroll 8
        for (int t = 0; t < CHUNK; t++)
            s += __half2float(ksb[t * APITCH + tid]);
        g_ksum[(bh * NCHUNK + c) * DH + tid] = s;
    }
}

// ---------------------------------------------------------------------------
// Kernel 3: exclusive prefix-sum over chunks -> S (fp16 hi) + z (fp32).
// Vectorized: each thread handles 2 consecutive elements (uint32 loads).
// grid (8, NBH), 256 threads.
// ---------------------------------------------------------------------------
__global__ __launch_bounds__(256)
void prefix_state2()
{
    const int bh = blockIdx.y;
    const int e2 = (blockIdx.x * 256 + threadIdx.x) * 2;
    const __half* src = g_KtVh + (size_t)bh * NCHUNK * (DH * DV) + e2;
    __half* dh = g_Sth + (size_t)bh * NCHUNK * (DH * DV) + e2;

    uint32_t v[NCHUNK];
    #pragma unroll
    for (int c = 0; c < NCHUNK; c++)
        v[c] = *(const uint32_t*)(src + c * (DH * DV));
    float a0 = 0.f, a1 = 0.f;
    #pragma unroll
    for (int c = 0; c < NCHUNK; c++) {
        *(uint32_t*)(dh + c * (DH * DV)) =
            pack_h2(__float2half_rn(a0), __float2half_rn(a1));
        __half2 hv = *(__half2*)&v[c];
        a0 += __half2float(__low2half(hv));
        a1 += __half2float(__high2half(hv));
    }

    if (blockIdx.x == 0 && threadIdx.x < DH) {
        const float* ks = g_ksum + bh * NCHUNK * DH + threadIdx.x;
        float wz[NCHUNK];
        #pragma unroll
        for (int c = 0; c < NCHUNK; c++) wz[c] = ks[c * DH];
        float a = 0.f;
        #pragma unroll
        for (int c = 0; c < NCHUNK; c++) {
            g_zpre[bh * NCHUNK * DH + c * DH + threadIdx.x] = a;
            a += wz[c];
        }
    }
}

// ---------------------------------------------------------------------------
// Kernel 4: per-chunk attention. grid (NCHUNK, NBH), 256 thr, 2 CTAs/SM.
// smem tiles: 0 Qh 1 Ql 2 Kh 3 Vh 4 Sh 5 Amh 6 Aml + z + den
// ---------------------------------------------------------------------------
#define SMEM_ATT_BYTES (7 * ATILE_B + 2 * 64 * 4)

__global__ __launch_bounds__(256, 2)
void attn_mma()
{
    extern __shared__ __half asb[];
    const uint32_t smb = smem_u32(asb);
    const int c  = blockIdx.x;
    const int bh = blockIdx.y;
    const int b  = bh >> 3, h = bh & 7;
    const int tid  = threadIdx.x;
    const int w    = tid >> 5;
    const int lane = tid & 31;
    const int g    = lane >> 2, q = lane & 3;
    const int sel  = lane >> 3, rr = lane & 7;
    const int wm   = (w >> 1) * 16;   // tau
    const int wn   = (w & 1) * 32;    // j / sigma

    float* zs  = (float*)(asb + 7 * ATILE_E);
    float* dns = zs + 64;

    const size_t grow = (size_t)(b * TSEQ + c * CHUNK);
    const __half* srcs[5] = {
        g_Qh + grow * DM + h * DH, g_Ql + grow * DM + h * DH,
        g_Kh + grow * DM + h * DH, g_Vh + grow * DM + h * DH,
        g_Sth + (size_t)(bh * NCHUNK + c) * (DH * DV) };
    #pragma unroll
    for (int t = 0; t < 5; t++) {
        const int sp = (t < 4) ? DM : DV;
        #pragma unroll
        for (int it = 0; it < 2; it++) {
            int idx = tid + it * 256;
            int r = idx >> 3, sg = idx & 7;
            *(uint4*)(asb + t * ATILE_E + r * APITCH + sg * 8) =
                *(const uint4*)(srcs[t] + (size_t)r * sp + sg * 8);
        }
    }
    if (tid < 64) zs[tid] = g_zpre[(bh * NCHUNK + c) * DH + tid];
    __syncthreads();

    const uint32_t aQ = smb +
        (uint32_t)(((wm + (sel & 1) * 8 + rr) * APITCH) + (sel >> 1) * 8) * 2;
    const uint32_t bK = smb + 2 * ATILE_B +
        (uint32_t)((((sel >> 1) * 8 + rr) * APITCH) + (sel & 1) * 8) * 2;
    const uint32_t bV = smb + 3 * ATILE_B +
        (uint32_t)((((sel & 1) * 8 + rr) * APITCH) + (sel >> 1) * 8) * 2;
    const uint32_t bS = smb + 4 * ATILE_B +
        (uint32_t)((((sel & 1) * 8 + rr) * APITCH) + (sel >> 1) * 8) * 2;
    const uint32_t aA = smb + 5 * ATILE_B +
        (uint32_t)(((wm + (sel & 1) * 8 + rr) * APITCH) + (sel >> 1) * 8) * 2;

    float o[4][4], a2[4][4];
    #pragma unroll
    for (int ni = 0; ni < 4; ni++)
        #pragma unroll
        for (int r = 0; r < 4; r++) { o[ni][r] = 0.f; a2[ni][r] = 0.f; }

    // ---- step A: A2 = Q K^T (2-term) and O = Q @ S (2-term) ----
    #pragma unroll
    for (int kk = 0; kk < 4; kk++) {
        const uint32_t ko = (uint32_t)kk * 32;
        const uint32_t kro = (uint32_t)kk * 16 * APITCH * 2;
        uint32_t ah[4], al[4], bhf[2][4];
        ldmx4(ah, aQ + ko);
        ldmx4(al, aQ + ATILE_B + ko);
        #pragma unroll
        for (int nb = 0; nb < 2; nb++)
            ldmx4(bhf[nb], bK + (uint32_t)(wn + nb * 16) * APITCH * 2 + ko);
        #pragma unroll
        for (int ni = 0; ni < 4; ni++)
            mma16816(a2[ni], ah, &bhf[ni >> 1][(ni & 1) * 2]);
        #pragma unroll
        for (int ni = 0; ni < 4; ni++)
            mma16816(a2[ni], al, &bhf[ni >> 1][(ni & 1) * 2]);
        #pragma unroll
        for (int nb = 0; nb < 2; nb++)
            ldmx4t(bhf[nb], bS + kro + (uint32_t)(wn + nb * 16) * 2);
        #pragma unroll
        for (int ni = 0; ni < 4; ni++)
            mma16816(o[ni], ah, &bhf[ni >> 1][(ni & 1) * 2]);
        #pragma unroll
        for (int ni = 0; ni < 4; ni++)
            mma16816(o[ni], al, &bhf[ni >> 1][(ni & 1) * 2]);
    }

    // mask + store A2 to smem as fp16 hi/lo
    #pragma unroll
    for (int ni = 0; ni < 4; ni++) {
        const int sig0 = wn + ni * 8 + 2 * q;
        const int tau0 = wm + g;
        float v0 = (sig0     <= tau0)     ? a2[ni][0] : 0.f;
        float v1 = (sig0 + 1 <= tau0)     ? a2[ni][1] : 0.f;
        float v2 = (sig0     <= tau0 + 8) ? a2[ni][2] : 0.f;
        float v3 = (sig0 + 1 <= tau0 + 8) ? a2[ni][3] : 0.f;
        uint32_t hi, lo;
        split2u(v0, v1, hi, lo);
        *(uint32_t*)(asb + 5 * ATILE_E + tau0 * APITCH + sig0) = hi;
        *(uint32_t*)(asb + 6 * ATILE_E + tau0 * APITCH + sig0) = lo;
        split2u(v2, v3, hi, lo);
        *(uint32_t*)(asb + 5 * ATILE_E + (tau0 + 8) * APITCH + sig0) = hi;
        *(uint32_t*)(asb + 6 * ATILE_E + (tau0 + 8) * APITCH + sig0) = lo;
    }
    __syncthreads();

    // den (2 warps) concurrently with step B on the others
    if (tid < 64) {
        float d = 0.f;
        #pragma unroll 8
        for (int i = 0; i < 64; i++)
            d += (__half2float(asb[tid * APITCH + i]) +
                  __half2float(asb[ATILE_E + tid * APITCH + i])) * zs[i];
        for (int s2 = 0; s2 <= tid; s2++)
            d += __half2float(asb[5 * ATILE_E + tid * APITCH + s2]) +
                 __half2float(asb[6 * ATILE_E + tid * APITCH + s2]);
        dns[tid] = fmaxf(d, 1e-6f);
    }

    // ---- step B: O += A2 @ V (V hi only) ----
    #pragma unroll
    for (int kk = 0; kk < 4; kk++) {
        const uint32_t ko = (uint32_t)kk * 32;
        const uint32_t kro = (uint32_t)kk * 16 * APITCH * 2;
        uint32_t ah[4], al[4], bhf[2][4];
        ldmx4(ah, aA + ko);
        ldmx4(al, aA + ATILE_B + ko);
        #pragma unroll
        for (int nb = 0; nb < 2; nb++)
            ldmx4t(bhf[nb], bV + kro + (uint32_t)(wn + nb * 16) * 2);
        #pragma unroll
        for (int ni = 0; ni < 4; ni++)
            mma16816(o[ni], ah, &bhf[ni >> 1][(ni & 1) * 2]);
        #pragma unroll
        for (int ni = 0; ni < 4; ni++)
            mma16816(o[ni], al, &bhf[ni >> 1][(ni & 1) * 2]);
    }
    __syncthreads();   // den ready

    // epilogue: normalize + write fp16 hi only (out-proj is 1-term)
    const float r0 = 1.f / dns[wm + g];
    const float r1 = 1.f / dns[wm + g + 8];
    #pragma unroll
    for (int ni = 0; ni < 4; ni++) {
        const int jj = wn + ni * 8 + 2 * q;
        *(uint32_t*)(g_Ah + (grow + wm + g) * DM + h * DV + jj) =
            pack_h2(__float2half_rn(o[ni][0] * r0), __float2half_rn(o[ni][1] * r0));
        *(uint32_t*)(g_Ah + (grow + wm + g + 8) * DM + h * DV + jj) =
            pack_h2(__float2half_rn(o[ni][2] * r1), __float2half_rn(o[ni][3] * r1));
    }
}

// ---------------------------------------------------------------------------
extern "C" void kernel_launch(void* const* d_in, const int* in_sizes, int n_in,
                              void* d_out, int out_size)
{
    const float* x    = (const float*)d_in[0];
    const float* Wq   = (const float*)d_in[1];
    const float* Wk   = (const float*)d_in[2];
    const float* Wv   = (const float*)d_in[3];
    const float* Wout = (const float*)d_in[4];
    float* out = (float*)d_out;

    cudaFuncSetAttribute(gemm_qkv_tc,
                         cudaFuncAttributeMaxDynamicSharedMemorySize,
                         SMEM_GEMM_BYTES);
    cudaFuncSetAttribute(gemm_out_tc,
                         cudaFuncAttributeMaxDynamicSharedMemorySize,
                         SMEM_GEMM_BYTES);
    cudaFuncSetAttribute(attn_mma,
                         cudaFuncAttributeMaxDynamicSharedMemorySize,
                         SMEM_ATT_BYTES);

    split_all<<<3072, 256>>>(x, Wq, Wk, Wv, Wout);                 // idx 0
    gemm_qkv_tc <<<GRID_PERS, NTHR, SMEM_GEMM_BYTES>>>();          // idx 1
    chunk_kv_mma <<<dim3(NCHUNK, NBH), 256, SMEM_KV_BYTES>>>();    // idx 2
    prefix_state2<<<dim3(8, NBH), 256>>>();                        // idx 3 (profiled)
    attn_mma     <<<dim3(NCHUNK, NBH), 256, SMEM_ATT_BYTES>>>();
    gemm_out_tc  <<<dim3(BT / 128, 4), NTHR, SMEM_GEMM_BYTES>>>(out);
}